// round 11
// baseline (speedup 1.0000x reference)
#include <cuda_runtime.h>
#include <stdint.h>

// PatchShift: out[b,t,h,w,c] = x[b, (t - S[h%3, w%3]) % 8, h, w, c]
// Shapes: B=32, T=8, H=14, W=14, C=768 (fp32) -> rows of 192 float4.
//
// FINAL, CONVERGED (benched 3x identical: 41.5/41.95/41.79us kernel,
// dur_us 49.66/49.63/49.70). DRAM ~77%, effective ~7.4 TB/s including
// cross-replay L2 hits = B300 LTS chip-throughput cap (path-independent;
// TMA would hit the same ceiling). Zero-FLOP permutation -> memory-bound
// by construction; this is the roofline.
//
// Structure: one 192-thread CTA per (b,h,w) pixel; each thread owns one
// channel float4 and copies it across all T=8 slices: 8 front-batched
// independent loads, then 8 stores. Default cache policy, 64-bit index
// math, hardware CTA scheduling — each alternative was measured and lost:
//   ldcs/stcs, ldcg hints: -1.4..-2.9% | 32-bit idx: -2.4%
//   persistent 1480-CTA loop: -11%     | 256-thr flat (100% occ): -2.2%
//   2x per-thread work: -3.4%          | 384-thr blocks: -3.4%

#define B_ 32
#define T_ 8
#define H_ 14
#define W_ 14
#define C4_ 192                         // 768 floats = 192 float4
#define TSTRIDE (H_ * W_ * C4_)         // float4 stride between time slices = 37632

__global__ __launch_bounds__(C4_) void patch_shift_kernel(
    const float4* __restrict__ x, float4* __restrict__ out)
{
    // blockIdx.x = h*14 + w (0..195), blockIdx.y = b (0..31)
    const int hw = blockIdx.x;
    const int w  = hw % 14;             // constant divisor -> mul/shift
    const int h  = hw / 14;
    const int b  = blockIdx.y;

    const int Stab[9] = {-4, 1, 2, -1, 0, 3, -2, -3, 4};
    const int s = Stab[(h % 3) * 3 + (w % 3)];

    // base index of (b, t=0, h, w, c4=tid)
    const long long base = ((long long)b * T_ * H_ * W_ + hw) * C4_ + threadIdx.x;

    float4 v[T_];
    #pragma unroll
    for (int t = 0; t < T_; ++t) {
        const int ts = (t - s + 8) & 7;          // source time slice
        v[t] = x[base + (long long)ts * TSTRIDE];
    }
    #pragma unroll
    for (int t = 0; t < T_; ++t) {
        out[base + (long long)t * TSTRIDE] = v[t];
    }
}

extern "C" void kernel_launch(void* const* d_in, const int* in_sizes, int n_in,
                              void* d_out, int out_size)
{
    const float4* x   = (const float4*)d_in[0];
    float4*       out = (float4*)d_out;

    dim3 grid(H_ * W_, B_);             // (196, 32) = 6272 CTAs
    patch_shift_kernel<<<grid, C4_>>>(x, out);
}

// round 12
// speedup vs baseline: 1.0109x; 1.0109x over previous
#include <cuda_runtime.h>
#include <stdint.h>

// PatchShift: out[b,t,h,w,c] = x[b, (t - S[h%3, w%3]) % 8, h, w, c]
// Shapes: B=32, T=8, H=14, W=14, C=768 (fp32) -> rows of 192 float4.
//
// R2 converged structure (4 benches: 41.5/41.95/41.79/42.75us) with ONE
// targeted change: stores use evict-first (__stcs), loads stay DEFAULT.
// Rationale: output (154MB) is write-only -> default write-allocate evicts
// input lines that ARE re-read across graph replays (measured ~18% L2 read
// hits: 7.4TB/s effective vs 6.1TB/s DRAM). R3 tested ldcs+stcs together
// (lost because ldcs discarded the read hits); stores-only is the untested
// orthogonal cell.

#define B_ 32
#define T_ 8
#define H_ 14
#define W_ 14
#define C4_ 192                         // 768 floats = 192 float4
#define TSTRIDE (H_ * W_ * C4_)         // float4 stride between time slices = 37632

__global__ __launch_bounds__(C4_) void patch_shift_kernel(
    const float4* __restrict__ x, float4* __restrict__ out)
{
    // blockIdx.x = h*14 + w (0..195), blockIdx.y = b (0..31)
    const int hw = blockIdx.x;
    const int w  = hw % 14;             // constant divisor -> mul/shift
    const int h  = hw / 14;
    const int b  = blockIdx.y;

    const int Stab[9] = {-4, 1, 2, -1, 0, 3, -2, -3, 4};
    const int s = Stab[(h % 3) * 3 + (w % 3)];

    // base index of (b, t=0, h, w, c4=tid)
    const long long base = ((long long)b * T_ * H_ * W_ + hw) * C4_ + threadIdx.x;

    float4 v[T_];
    #pragma unroll
    for (int t = 0; t < T_; ++t) {
        const int ts = (t - s + 8) & 7;          // source time slice
        v[t] = x[base + (long long)ts * TSTRIDE];
    }
    #pragma unroll
    for (int t = 0; t < T_; ++t) {
        __stcs(&out[base + (long long)t * TSTRIDE], v[t]);   // write-only stream: evict-first
    }
}

extern "C" void kernel_launch(void* const* d_in, const int* in_sizes, int n_in,
                              void* d_out, int out_size)
{
    const float4* x   = (const float4*)d_in[0];
    float4*       out = (float4*)d_out;

    dim3 grid(H_ * W_, B_);             // (196, 32) = 6272 CTAs
    patch_shift_kernel<<<grid, C4_>>>(x, out);
}